// round 7
// baseline (speedup 1.0000x reference)
#include <cuda_runtime.h>
#include <cstdint>

// sim[b,o] = sum_d |x[b,d] - c[o,d]|;  out[b,o] = beta[o] * (max(sim)*1.001 - sim[b,o])
// x[1024,512], centers[512,512], beta[512] fp32 -> out fp32 [1024,512].
// R6: 1024 CTAs x 64 threads (BM=32,BN=16), 4x2 frag, cp.async 3-stage pipeline,
// float4 smem + LDS.128, packed f32x2 math, spin grid barrier, epilogue in regs.

#define BM 32
#define BN 16
#define KC 32
#define NQ (KC / 4)        // float4 quads per chunk
#define STAGES 3
#define W_DIST 1.001f

typedef unsigned long long u64;

#define ABSM 0x7FFFFFFF7FFFFFFFULL
#define NEG1 0xBF800000BF800000ULL   // packed {-1.0f, -1.0f}

__device__ int      g_max_bits = 0;   // sims > 0 -> int order == float order
__device__ unsigned g_count1   = 0;
__device__ unsigned g_count2   = 0;

__device__ __forceinline__ u64 addx2(u64 a, u64 b) {
    u64 r; asm("add.rn.f32x2 %0, %1, %2;" : "=l"(r) : "l"(a), "l"(b)); return r;
}
__device__ __forceinline__ u64 fma2(u64 a, u64 b, u64 c) {
    u64 r; asm("fma.rn.f32x2 %0, %1, %2, %3;" : "=l"(r) : "l"(a), "l"(b), "l"(c)); return r;
}
__device__ __forceinline__ void cp16(float4* dst, const float4* src) {
    unsigned d = (unsigned)__cvta_generic_to_shared(dst);
    asm volatile("cp.async.cg.shared.global [%0], [%1], 16;" :: "r"(d), "l"(src));
}
#define CP_COMMIT() asm volatile("cp.async.commit_group;")
#define CP_WAIT1()  asm volatile("cp.async.wait_group 1;")

__global__ __launch_bounds__(64, 8) void rbf_fused_kernel(
    const float* __restrict__ x,
    const float* __restrict__ c,
    const float* __restrict__ beta,
    float* __restrict__ out,
    int DIN, int DOUT, int NTN, unsigned NB)
{
    // [stage][quad][row] float4, +1 row pad -> conflict-free STS (cp.async) and LDS.128
    __shared__ float4 xs[STAGES][NQ][BM + 1];
    __shared__ float4 cs[STAGES][NQ][BN + 1];
    __shared__ float  wmax[2];
    __shared__ float  s_gm;

    const int tid = threadIdx.x;
    const int bid = blockIdx.x;
    const int bm = bid / NTN;
    const int bn = bid % NTN;
    const int tr = tid >> 3;           // 0..7  -> m = tr + 8*i (i<4)
    const int tc = tid & 7;            // 0..7  -> n = tc + 8*j (j<2)

    const int qpr = DIN / 4;           // float4 quads per gmem row
    const float4* xgb = reinterpret_cast<const float4*>(x) + (size_t)(bm * BM) * qpr;
    const float4* cgb = reinterpret_cast<const float4*>(c) + (size_t)(bn * BN) * qpr;
    const int nchunks = DIN / KC;      // 16

    auto fill = [&](int st, int ch) {
        const int kq = ch * NQ;
#pragma unroll
        for (int k = 0; k < 4; k++) {  // x tile: 32 rows x 8 quads = 256 f4 / 64 thr
            int idx = k * 64 + tid;
            int row = idx >> 3, q = idx & 7;
            cp16(&xs[st][q][row], xgb + (size_t)row * qpr + kq + q);
        }
#pragma unroll
        for (int k = 0; k < 2; k++) {  // c tile: 16 rows x 8 quads = 128 f4 / 64 thr
            int idx = k * 64 + tid;
            int row = idx >> 3, q = idx & 7;
            cp16(&cs[st][q][row], cgb + (size_t)row * qpr + kq + q);
        }
    };

    fill(0, 0); CP_COMMIT();
    fill(1, 1); CP_COMMIT();

    u64 acc[4][2];
#pragma unroll
    for (int i = 0; i < 4; i++)
#pragma unroll
        for (int j = 0; j < 2; j++) acc[i][j] = 0ULL;

    for (int ch = 0; ch < nchunks; ch++) {
        const int st = ch % STAGES;
        CP_WAIT1();                       // chunk ch resident (<=1 group still in flight)
        __syncthreads();                  // all warps past compute(ch-1); data visible
        if (ch + 2 < nchunks) {           // refill buffer (ch+2)%3 == (ch-1)%3 (safe: barrier above)
            fill((ch + 2) % STAGES, ch + 2);
            CP_COMMIT();
        }

#pragma unroll
        for (int p2 = 0; p2 < NQ; p2++) {  // one float4 = 2 k-pairs = 4 k-elements
            float4 xa[4], cb[2];
#pragma unroll
            for (int i = 0; i < 4; i++) xa[i] = xs[st][p2][tr + 8 * i];
#pragma unroll
            for (int j = 0; j < 2; j++) cb[j] = cs[st][p2][tc + 8 * j];
#pragma unroll
            for (int i = 0; i < 4; i++) {
                const u64* au = reinterpret_cast<const u64*>(&xa[i]);
#pragma unroll
                for (int j = 0; j < 2; j++) {
                    const u64* bu = reinterpret_cast<const u64*>(&cb[j]);
                    u64 d0 = fma2(bu[0], NEG1, au[0]) & ABSM;  // x - c, |.| packed
                    u64 d1 = fma2(bu[1], NEG1, au[1]) & ABSM;
                    acc[i][j] = addx2(acc[i][j], d0);
                    acc[i][j] = addx2(acc[i][j], d1);
                }
            }
        }
    }

    // ---- per-thread sim fragment + block max ----
    float s[4][2];
    float tmax = 0.0f;
#pragma unroll
    for (int i = 0; i < 4; i++)
#pragma unroll
        for (int j = 0; j < 2; j++) {
            float2 v = *reinterpret_cast<float2*>(&acc[i][j]);
            s[i][j] = v.x + v.y;
            tmax = fmaxf(tmax, s[i][j]);
        }
#pragma unroll
    for (int off = 16; off > 0; off >>= 1)
        tmax = fmaxf(tmax, __shfl_xor_sync(0xffffffffu, tmax, off));
    if ((tid & 31) == 0) wmax[tid >> 5] = tmax;
    __syncthreads();

    // beta loads issued before the spin to hide their latency
    float bet[2];
#pragma unroll
    for (int j = 0; j < 2; j++) bet[j] = beta[bn * BN + tc + 8 * j];

    // ---- grid barrier: all 1024 CTAs co-resident (launch_bounds(64,8); 1024 <= 8*148) ----
    if (tid == 0) {
        float bmx = fmaxf(wmax[0], wmax[1]);
        atomicMax(&g_max_bits, __float_as_int(bmx));
        __threadfence();
        atomicAdd(&g_count1, 1u);
        while (*((volatile unsigned*)&g_count1) < NB) { __nanosleep(64); }
        __threadfence();
        s_gm = __int_as_float(*((volatile int*)&g_max_bits)) * W_DIST;
        unsigned old = atomicAdd(&g_count2, 1u);   // last consumer resets for next replay
        if (old == NB - 1u) {
            g_max_bits = 0;
            g_count1   = 0;
            g_count2   = 0;
        }
    }
    __syncthreads();
    const float gm = s_gm;

    // ---- epilogue from registers ----
#pragma unroll
    for (int i = 0; i < 4; i++) {
        const int row = bm * BM + tr + 8 * i;
        float* orow = out + (size_t)row * DOUT + bn * BN;
#pragma unroll
        for (int j = 0; j < 2; j++)
            orow[tc + 8 * j] = bet[j] * (gm - s[i][j]);
    }
}

extern "C" void kernel_launch(void* const* d_in, const int* in_sizes, int n_in,
                              void* d_out, int out_size)
{
    const float* x    = (const float*)d_in[0];
    const float* c    = (const float*)d_in[1];
    const float* beta = (const float*)d_in[2];
    float* out = (float*)d_out;

    const int DOUT = in_sizes[2];
    const int DIN  = in_sizes[1] / DOUT;
    const int B    = in_sizes[0] / DIN;

    const int NTN = DOUT / BN;                 // 32
    const unsigned NB = (unsigned)((B / BM) * NTN);  // 1024
    rbf_fused_kernel<<<NB, 64>>>(x, c, beta, out, DIN, DOUT, NTN, NB);
}

// round 8
// speedup vs baseline: 1.2797x; 1.2797x over previous
#include <cuda_runtime.h>
#include <cstdint>

// sim[b,o] = sum_d |x[b,d] - c[o,d]|;  out[b,o] = beta[o] * (max(sim)*1.001 - sim[b,o])
// x[1024,512], centers[512,512], beta[512] fp32 -> out fp32 [1024,512].
// R8 = R5 geometry (512 CTAs, 32x32 tiles, 128 thr, 4 CTA/SM, grid barrier)
//      + float4 smem layout (conflict-free STS.128/LDS.128) + halved LDS issue count.

#define BM 32
#define BN 32
#define KC 32
#define NQ (KC / 4)        // 8 float4 quads per chunk
#define W_DIST 1.001f

typedef unsigned long long u64;
#define ABSM 0x7FFFFFFF7FFFFFFFULL
#define NEG1 0xBF800000BF800000ULL   // packed {-1.0f,-1.0f}

__device__ int      g_max_bits = 0;   // sims > 0 -> int order == float order
__device__ unsigned g_count1   = 0;
__device__ unsigned g_count2   = 0;

__device__ __forceinline__ u64 addx2(u64 a, u64 b) {
    u64 r; asm("add.rn.f32x2 %0, %1, %2;" : "=l"(r) : "l"(a), "l"(b)); return r;
}
__device__ __forceinline__ u64 fma2(u64 a, u64 b, u64 c) {
    u64 r; asm("fma.rn.f32x2 %0, %1, %2, %3;" : "=l"(r) : "l"(a), "l"(b), "l"(c)); return r;
}

__global__ __launch_bounds__(128, 4) void rbf_fused_kernel(
    const float* __restrict__ x,
    const float* __restrict__ c,
    const float* __restrict__ beta,
    float* __restrict__ out,
    int DIN, int DOUT, unsigned NB)
{
    // [buf][quad][row(+1 pad)] float4 — pad makes STS.128 fill (q=tid&7,row=tid>>3)
    // hit banks 4q mod 32 (distinct per phase) and keeps LDS.128 reads conflict-free.
    __shared__ float4 xs[2][NQ][BM + 1];   // ~8.4 KB
    __shared__ float4 cs[2][NQ][BN + 1];   // ~8.4 KB
    __shared__ float  wmax[4];
    __shared__ float  s_gm;

    const int tid = threadIdx.x;
    const int bm = blockIdx.y;
    const int bn = blockIdx.x;
    const int tr = tid >> 4;           // 0..7  -> m = tr + 8*i (i<4)
    const int tc = tid & 15;           // 0..15 -> n = tc + 16*j (j<2)

    u64 acc[4][2];
#pragma unroll
    for (int i = 0; i < 4; i++)
#pragma unroll
        for (int j = 0; j < 2; j++) acc[i][j] = 0ULL;

    // fill mapping: each thread owns (quad fq, rows fr and fr+16) in both tiles
    const int fq = tid & 7;            // 0..7
    const int fr = tid >> 3;           // 0..15
    const int qpr = DIN / 4;
    const float4* xg0 = reinterpret_cast<const float4*>(x) + (size_t)(bm * BM + fr)      * qpr + fq;
    const float4* xg1 = reinterpret_cast<const float4*>(x) + (size_t)(bm * BM + fr + 16) * qpr + fq;
    const float4* cg0 = reinterpret_cast<const float4*>(c) + (size_t)(bn * BN + fr)      * qpr + fq;
    const float4* cg1 = reinterpret_cast<const float4*>(c) + (size_t)(bn * BN + fr + 16) * qpr + fq;

    float4 vx0 = *xg0, vx1 = *xg1, vc0 = *cg0, vc1 = *cg1;

    // prologue: fill buffer 0 (conflict-free STS.128)
    xs[0][fq][fr]      = vx0;
    xs[0][fq][fr + 16] = vx1;
    cs[0][fq][fr]      = vc0;
    cs[0][fq][fr + 16] = vc1;
    __syncthreads();

    const int nchunks = DIN / KC;      // 16
    for (int ch = 0; ch < nchunks; ch++) {
        const int pb = ch & 1;
        if (ch + 1 < nchunks) {        // register prefetch of next chunk
            const int off = (ch + 1) * NQ;
            vx0 = xg0[off]; vx1 = xg1[off];
            vc0 = cg0[off]; vc1 = cg1[off];
        }

#pragma unroll
        for (int p2 = 0; p2 < NQ; p2++) {      // one float4 = 4 k-elements
            float4 xa[4], cb[2];
#pragma unroll
            for (int i = 0; i < 4; i++) xa[i] = xs[pb][p2][tr + 8 * i];      // broadcast
#pragma unroll
            for (int j = 0; j < 2; j++) cb[j] = cs[pb][p2][tc + 16 * j];     // wait: tc+16j<33? j=1 -> tc+16 <= 31 OK
#pragma unroll
            for (int i = 0; i < 4; i++) {
                const u64* au = reinterpret_cast<const u64*>(&xa[i]);
#pragma unroll
                for (int j = 0; j < 2; j++) {
                    const u64* bu = reinterpret_cast<const u64*>(&cb[j]);
                    u64 d0 = fma2(bu[0], NEG1, au[0]) & ABSM;   // |x - c| packed (lo pair)
                    u64 d1 = fma2(bu[1], NEG1, au[1]) & ABSM;   // |x - c| packed (hi pair)
                    acc[i][j] = addx2(acc[i][j], d0);
                    acc[i][j] = addx2(acc[i][j], d1);
                }
            }
        }

        if (ch + 1 < nchunks) {        // store prefetched chunk into the other buffer
            const int nb = 1 - pb;
            xs[nb][fq][fr]      = vx0;
            xs[nb][fq][fr + 16] = vx1;
            cs[nb][fq][fr]      = vc0;
            cs[nb][fq][fr + 16] = vc1;
        }
        __syncthreads();
    }

    // ---- per-thread sim fragment + block max ----
    float s[4][2];
    float tmax = 0.0f;
#pragma unroll
    for (int i = 0; i < 4; i++)
#pragma unroll
        for (int j = 0; j < 2; j++) {
            float2 v = *reinterpret_cast<float2*>(&acc[i][j]);
            s[i][j] = v.x + v.y;
            tmax = fmaxf(tmax, s[i][j]);
        }
#pragma unroll
    for (int off = 16; off > 0; off >>= 1)
        tmax = fmaxf(tmax, __shfl_xor_sync(0xffffffffu, tmax, off));
    if ((tid & 31) == 0) wmax[tid >> 5] = tmax;
    __syncthreads();

    // beta load before the spin (latency hidden under the barrier wait)
    float bet[2];
#pragma unroll
    for (int j = 0; j < 2; j++) bet[j] = beta[bn * BN + tc + 16 * j];

    // ---- grid barrier (all 512 CTAs co-resident: launch_bounds(128,4), 512 <= 4*148) ----
    if (tid == 0) {
        float bmx = fmaxf(fmaxf(wmax[0], wmax[1]), fmaxf(wmax[2], wmax[3]));
        atomicMax(&g_max_bits, __float_as_int(bmx));
        __threadfence();
        atomicAdd(&g_count1, 1u);
        while (*((volatile unsigned*)&g_count1) < NB) { __nanosleep(64); }
        __threadfence();
        s_gm = __int_as_float(*((volatile int*)&g_max_bits)) * W_DIST;
        unsigned old = atomicAdd(&g_count2, 1u);   // last consumer resets for next graph replay
        if (old == NB - 1u) {
            g_max_bits = 0;
            g_count1   = 0;
            g_count2   = 0;
        }
    }
    __syncthreads();
    const float gm = s_gm;

    // ---- epilogue from registers ----
#pragma unroll
    for (int i = 0; i < 4; i++) {
        const int row = bm * BM + tr + 8 * i;
        float* orow = out + (size_t)row * DOUT + bn * BN;
#pragma unroll
        for (int j = 0; j < 2; j++)
            orow[tc + 16 * j] = bet[j] * (gm - s[i][j]);
    }
}

extern "C" void kernel_launch(void* const* d_in, const int* in_sizes, int n_in,
                              void* d_out, int out_size)
{
    const float* x    = (const float*)d_in[0];
    const float* c    = (const float*)d_in[1];
    const float* beta = (const float*)d_in[2];
    float* out = (float*)d_out;

    const int DOUT = in_sizes[2];
    const int DIN  = in_sizes[1] / DOUT;
    const int B    = in_sizes[0] / DIN;

    dim3 grid(DOUT / BN, B / BM);
    const unsigned NB = grid.x * grid.y;   // 512
    rbf_fused_kernel<<<grid, 128>>>(x, c, beta, out, DIN, DOUT, NB);
}